// round 2
// baseline (speedup 1.0000x reference)
#include <cuda_runtime.h>
#include <math.h>

#define S_LEN 512
#define B_SZ  64
#define HID   1024
#define G4    4096      // 4*HID
#define NACT  128
#define NBLK  128       // persistent scan blocks (<= SM count, all co-resident)
#define UPB   8         // hidden units per block (NBLK*UPB = HID)
#define BK    16        // k-chunk

// ---------------- scratch (device globals; no allocations allowed) ----------
__device__ float g_gx[S_LEN * B_SZ * G4];       // [s][b][4H]
__device__ float g_hs[B_SZ * S_LEN * HID];      // [b][s][H]
__device__ float g_h2[2][B_SZ * HID];           // double-buffered h
__device__ float g_c [B_SZ * HID];
__device__ unsigned g_arrive;
__device__ unsigned g_release;

// ---------------- init: zero state, reset barrier, zero dummy outputs -------
__global__ void init_kernel(float* __restrict__ out, int has_dummy) {
    int i = blockIdx.x * 256 + threadIdx.x;          // 65536 threads
    g_c[i] = 0.f;
    g_h2[0][i] = 0.f;
    g_h2[1][i] = 0.f;
    if (i == 0) { g_arrive = 0u; g_release = 0u; }
    if (has_dummy && i < 2 * B_SZ * S_LEN) {
        int off = (i < B_SZ * S_LEN) ? i : (B_SZ * S_LEN * NACT + i);
        out[off] = 0.f;
    }
}

// ---------------- phase 1: gx[s][b][g] = embed[x[b][s]] @ Wi ----------------
// M = S*B = 32768 (m = s*64+b), N = 4096, K = 1024
__global__ __launch_bounds__(256) void gemm_gx(const float* __restrict__ embed,
                                               const float* __restrict__ Wi,
                                               const int*   __restrict__ x) {
    __shared__ float As[8][128];
    __shared__ float Bs[8][64];
    __shared__ int   rows[128];

    const int bn = blockIdx.x * 64;
    const int bm = blockIdx.y * 128;
    const int t  = threadIdx.x;
    const int tx = t & 15, ty = t >> 4;

    if (t < 128) {
        int m = bm + t;
        int b = m & 63, s = m >> 6;
        rows[t] = x[b * S_LEN + s] * HID;
    }

    float acc[8][4];
#pragma unroll
    for (int i = 0; i < 8; i++)
#pragma unroll
        for (int j = 0; j < 4; j++) acc[i][j] = 0.f;

    const int la_r = t >> 1;
    const int la_k = (t & 1) * 4;
    const int lb_k = t >> 5;
    const int lb_n = (t & 31) * 2;

    for (int k0 = 0; k0 < HID; k0 += 8) {
        __syncthreads();
        float4 av = *(const float4*)&embed[rows[la_r] + k0 + la_k];
        As[la_k + 0][la_r] = av.x;
        As[la_k + 1][la_r] = av.y;
        As[la_k + 2][la_r] = av.z;
        As[la_k + 3][la_r] = av.w;
        float2 bv = *(const float2*)&Wi[(k0 + lb_k) * G4 + bn + lb_n];
        *(float2*)&Bs[lb_k][lb_n] = bv;
        __syncthreads();
#pragma unroll
        for (int kk = 0; kk < 8; kk++) {
            float4 a0 = *(const float4*)&As[kk][ty * 8];
            float4 a1 = *(const float4*)&As[kk][ty * 8 + 4];
            float4 b0 = *(const float4*)&Bs[kk][tx * 4];
            float a[8] = {a0.x, a0.y, a0.z, a0.w, a1.x, a1.y, a1.z, a1.w};
            float b[4] = {b0.x, b0.y, b0.z, b0.w};
#pragma unroll
            for (int i = 0; i < 8; i++)
#pragma unroll
                for (int j = 0; j < 4; j++) acc[i][j] += a[i] * b[j];
        }
    }
#pragma unroll
    for (int i = 0; i < 8; i++) {
        float4 v = make_float4(acc[i][0], acc[i][1], acc[i][2], acc[i][3]);
        *(float4*)&g_gx[(size_t)(bm + ty * 8 + i) * G4 + bn + tx * 4] = v;
    }
}

// ---------------- persistent scan: 512 steps, one launch ---------------------
// Block bk owns hidden units [bk*8, bk*8+8). Per step:
//   gates[64][4 gates x 8 units] = h(prev) @ Wh(cols) ; pointwise -> c,h(next)
__device__ __forceinline__ void grid_barrier(unsigned epoch) {
    __syncthreads();
    if (threadIdx.x == 0) {
        __threadfence();
        unsigned prev = atomicAdd(&g_arrive, 1u);
        if (prev + 1u == (unsigned)NBLK * epoch) {
            atomicExch(&g_release, epoch);
        } else {
            unsigned r;
            do {
                asm volatile("ld.acquire.gpu.u32 %0, [%1];"
                             : "=r"(r) : "l"(&g_release) : "memory");
            } while (r < epoch);
        }
    }
    __syncthreads();
}

__global__ __launch_bounds__(256, 1) void scan_kernel(const float* __restrict__ Wh,
                                                      const float* __restrict__ bh) {
    __shared__ float Hs[64][BK + 1];        // h tile, padded (conflict-free)
    __shared__ float Ws[4][BK][UPB];        // Wh tile: 4 gates x BK k x 8 units
    __shared__ float gsm[4][64][UPB];       // gate exchange

    const int t  = threadIdx.x;
    const int j0 = blockIdx.x * UPB;
    const int r  = t & 63;                  // batch row for GEMM
    const int gg = t >> 6;                  // gate id for GEMM

    // load indices
    const int hl_r  = t >> 2;               // 0..63
    const int hl_k4 = (t & 3) * 4;          // 0,4,8,12
    const int wl_g  = t >> 5;               // 0..3 (t<128)
    const int wl_kk = (t & 31) >> 1;        // 0..15
    const int wl_h  = (t & 1) * 4;          // 0 or 4

    for (int s = 0; s < S_LEN; ++s) {
        const float* hbuf = g_h2[s & 1];
        float acc[UPB];
#pragma unroll
        for (int u = 0; u < UPB; u++) acc[u] = 0.f;

        for (int k0 = 0; k0 < HID; k0 += BK) {
            __syncthreads();
            float4 hv = *(const float4*)&hbuf[hl_r * HID + k0 + hl_k4];
            Hs[hl_r][hl_k4 + 0] = hv.x;
            Hs[hl_r][hl_k4 + 1] = hv.y;
            Hs[hl_r][hl_k4 + 2] = hv.z;
            Hs[hl_r][hl_k4 + 3] = hv.w;
            if (t < 128) {
                float4 wv = *(const float4*)&Wh[(size_t)(k0 + wl_kk) * G4 +
                                                wl_g * HID + j0 + wl_h];
                Ws[wl_g][wl_kk][wl_h + 0] = wv.x;
                Ws[wl_g][wl_kk][wl_h + 1] = wv.y;
                Ws[wl_g][wl_kk][wl_h + 2] = wv.z;
                Ws[wl_g][wl_kk][wl_h + 3] = wv.w;
            }
            __syncthreads();
#pragma unroll
            for (int kk = 0; kk < BK; kk++) {
                float a = Hs[r][kk];
                float4 b0 = *(const float4*)&Ws[gg][kk][0];
                float4 b1 = *(const float4*)&Ws[gg][kk][4];
                acc[0] += a * b0.x; acc[1] += a * b0.y;
                acc[2] += a * b0.z; acc[3] += a * b0.w;
                acc[4] += a * b1.x; acc[5] += a * b1.y;
                acc[6] += a * b1.z; acc[7] += a * b1.w;
            }
        }
        __syncthreads();
#pragma unroll
        for (int u = 0; u < UPB; u++) gsm[gg][r][u] = acc[u];
        __syncthreads();

        // pointwise: 64 rows x 8 units = 512 elems, 2 per thread
        float* hnext = g_h2[(s + 1) & 1];
#pragma unroll
        for (int e2 = 0; e2 < 2; e2++) {
            int e = t + e2 * 256;
            int pr = e >> 3, u = e & 7;
            int j = j0 + u;
            const float* gx = &g_gx[((size_t)s * B_SZ + pr) * G4];
            float gi = gsm[0][pr][u] + gx[j]            + bh[j];
            float gf = gsm[1][pr][u] + gx[HID + j]      + bh[HID + j];
            float gv = gsm[2][pr][u] + gx[2 * HID + j]  + bh[2 * HID + j];
            float go = gsm[3][pr][u] + gx[3 * HID + j]  + bh[3 * HID + j];
            gi = 1.f / (1.f + expf(-gi));
            gf = 1.f / (1.f + expf(-gf));
            gv = tanhf(gv);
            go = 1.f / (1.f + expf(-go));
            float c = gf * g_c[pr * HID + j] + gi * gv;
            float h = go * tanhf(c);
            g_c[pr * HID + j] = c;
            hnext[pr * HID + j] = h;
            g_hs[((size_t)pr * S_LEN + s) * HID + j] = h;
        }
        grid_barrier((unsigned)(s + 1));
    }
}

// ---------------- phase 3: logits = hs @ Wo + bo ----------------------------
__global__ __launch_bounds__(256) void gemm_logits(const float* __restrict__ Wo,
                                                   const float* __restrict__ bo,
                                                   float* __restrict__ out) {
    __shared__ float As[8][128];
    __shared__ float Bs[8][64];

    const int bn = blockIdx.x * 64;
    const int bm = blockIdx.y * 128;
    const int t  = threadIdx.x;
    const int tx = t & 15, ty = t >> 4;

    float acc[8][4];
#pragma unroll
    for (int i = 0; i < 8; i++)
#pragma unroll
        for (int j = 0; j < 4; j++) acc[i][j] = 0.f;

    const int la_r = t >> 1;
    const int la_k = (t & 1) * 4;
    const int lb_k = t >> 5;
    const int lb_n = (t & 31) * 2;

    for (int k0 = 0; k0 < HID; k0 += 8) {
        __syncthreads();
        float4 av = *(const float4*)&g_hs[(size_t)(bm + la_r) * HID + k0 + la_k];
        As[la_k + 0][la_r] = av.x;
        As[la_k + 1][la_r] = av.y;
        As[la_k + 2][la_r] = av.z;
        As[la_k + 3][la_r] = av.w;
        float2 bv = *(const float2*)&Wo[(k0 + lb_k) * NACT + bn + lb_n];
        *(float2*)&Bs[lb_k][lb_n] = bv;
        __syncthreads();
#pragma unroll
        for (int kk = 0; kk < 8; kk++) {
            float4 a0 = *(const float4*)&As[kk][ty * 8];
            float4 a1 = *(const float4*)&As[kk][ty * 8 + 4];
            float4 b0 = *(const float4*)&Bs[kk][tx * 4];
            float a[8] = {a0.x, a0.y, a0.z, a0.w, a1.x, a1.y, a1.z, a1.w};
            float b[4] = {b0.x, b0.y, b0.z, b0.w};
#pragma unroll
            for (int i = 0; i < 8; i++)
#pragma unroll
                for (int j = 0; j < 4; j++) acc[i][j] += a[i] * b[j];
        }
    }
    float b0 = bo[bn + tx * 4 + 0];
    float b1 = bo[bn + tx * 4 + 1];
    float b2 = bo[bn + tx * 4 + 2];
    float b3 = bo[bn + tx * 4 + 3];
#pragma unroll
    for (int i = 0; i < 8; i++) {
        float4 v = make_float4(acc[i][0] + b0, acc[i][1] + b1,
                               acc[i][2] + b2, acc[i][3] + b3);
        *(float4*)&out[(size_t)(bm + ty * 8 + i) * NACT + bn + tx * 4] = v;
    }
}

// ---------------- launch -----------------------------------------------------
extern "C" void kernel_launch(void* const* d_in, const int* in_sizes, int n_in,
                              void* d_out, int out_size) {
    const float* embed = (const float*)d_in[0];
    const float* Wi    = (const float*)d_in[1];
    const float* Wh    = (const float*)d_in[2];
    const float* bh    = (const float*)d_in[3];
    const float* Wo    = (const float*)d_in[4];
    const float* bo    = (const float*)d_in[5];
    const int*   x     = (const int*)d_in[6];
    float* out = (float*)d_out;

    int has_dummy = (out_size == B_SZ * S_LEN * (NACT + 2)) ? 1 : 0;
    int logits_off = has_dummy ? B_SZ * S_LEN : 0;

    init_kernel<<<256, 256>>>(out, has_dummy);
    gemm_gx<<<dim3(G4 / 64, (S_LEN * B_SZ) / 128), 256>>>(embed, Wi, x);
    scan_kernel<<<NBLK, 256>>>(Wh, bh);
    gemm_logits<<<dim3(NACT / 64, (S_LEN * B_SZ) / 128), 256>>>(Wo, bo, out + logits_off);
}

// round 3
// speedup vs baseline: 1.3055x; 1.3055x over previous
#include <cuda_runtime.h>
#include <cuda_bf16.h>
#include <math.h>
#include <stdint.h>

#define S_LEN 512
#define B_SZ  64
#define HID   1024
#define G4    4096
#define NACT  128
#define NBLK  128       // persistent scan blocks
#define UPB   8         // hidden units per scan block
#define CH    128       // scan h-chunk (k)

// ---------------- scratch ----------------------------------------------------
__device__ float g_gx[(size_t)S_LEN * B_SZ * G4];   // [s][b][4H]
__device__ float g_hs[(size_t)B_SZ * S_LEN * HID];  // [b][s][H]
__device__ float g_h2[2][B_SZ * HID];
__device__ float g_c [B_SZ * HID];
__device__ unsigned g_arrive;
__device__ unsigned g_release;

// ---------------- init -------------------------------------------------------
__global__ void init_kernel(float* __restrict__ out, int has_dummy) {
    int i = blockIdx.x * 256 + threadIdx.x;          // 65536 threads
    g_c[i] = 0.f;
    g_h2[0][i] = 0.f;
    g_h2[1][i] = 0.f;
    if (i == 0) { g_arrive = 0u; g_release = 0u; }
    if (has_dummy && i < 2 * B_SZ * S_LEN) {
        int off = (i < B_SZ * S_LEN) ? i : (B_SZ * S_LEN * NACT + i);
        out[off] = 0.f;
    }
}

// ---------------- mma helpers ------------------------------------------------
__device__ __forceinline__ uint32_t smem_u32(const void* p) {
    return (uint32_t)__cvta_generic_to_shared(p);
}
__device__ __forceinline__ void ldsm_x4(uint32_t a, uint32_t& r0, uint32_t& r1,
                                        uint32_t& r2, uint32_t& r3) {
    asm volatile("ldmatrix.sync.aligned.m8n8.x4.shared.b16 {%0,%1,%2,%3}, [%4];"
                 : "=r"(r0), "=r"(r1), "=r"(r2), "=r"(r3) : "r"(a));
}
__device__ __forceinline__ void ldsm_x4t(uint32_t a, uint32_t& r0, uint32_t& r1,
                                         uint32_t& r2, uint32_t& r3) {
    asm volatile("ldmatrix.sync.aligned.m8n8.x4.trans.shared.b16 {%0,%1,%2,%3}, [%4];"
                 : "=r"(r0), "=r"(r1), "=r"(r2), "=r"(r3) : "r"(a));
}
__device__ __forceinline__ void mma16816(float* c, const uint32_t* a, const uint32_t* b) {
    asm volatile("mma.sync.aligned.m16n8k16.row.col.f32.bf16.bf16.f32 "
                 "{%0,%1,%2,%3},{%4,%5,%6,%7},{%8,%9},{%0,%1,%2,%3};"
                 : "+f"(c[0]), "+f"(c[1]), "+f"(c[2]), "+f"(c[3])
                 : "r"(a[0]), "r"(a[1]), "r"(a[2]), "r"(a[3]), "r"(b[0]), "r"(b[1]));
}
__device__ __forceinline__ uint32_t packbf(__nv_bfloat16 lo, __nv_bfloat16 hi) {
    return (uint32_t)__bfloat16_as_ushort(lo) | ((uint32_t)__bfloat16_as_ushort(hi) << 16);
}
// split float4 into hi/lo bf16 pairs (two uint32 each)
__device__ __forceinline__ void split4(float4 v, uint32_t& h0, uint32_t& h1,
                                       uint32_t& l0, uint32_t& l1) {
    __nv_bfloat16 a = __float2bfloat16(v.x), b = __float2bfloat16(v.y);
    __nv_bfloat16 c = __float2bfloat16(v.z), d = __float2bfloat16(v.w);
    __nv_bfloat16 ra = __float2bfloat16(v.x - __bfloat162float(a));
    __nv_bfloat16 rb = __float2bfloat16(v.y - __bfloat162float(b));
    __nv_bfloat16 rc = __float2bfloat16(v.z - __bfloat162float(c));
    __nv_bfloat16 rd = __float2bfloat16(v.w - __bfloat162float(d));
    h0 = packbf(a, b); h1 = packbf(c, d);
    l0 = packbf(ra, rb); l1 = packbf(rc, rd);
}

// ---------------- phase 1: gx = embed[x] @ Wi via bf16-split tensor cores ----
// M=32768 (m = s*64+b), N=4096, K=1024.  BM=128 BN=128 BK=32, 256 thr (8 warps)
#define ASTR 40    // As row stride (bf16)
#define BSTR 136   // Bs row stride (bf16)
__global__ __launch_bounds__(256) void gemm_gx(const float* __restrict__ embed,
                                               const float* __restrict__ Wi,
                                               const int*   __restrict__ x) {
    __shared__ __align__(16) unsigned short AsH[128][ASTR];
    __shared__ __align__(16) unsigned short AsL[128][ASTR];
    __shared__ __align__(16) unsigned short BsH[32][BSTR];
    __shared__ __align__(16) unsigned short BsL[32][BSTR];
    __shared__ int rows[128];

    const int bn = blockIdx.x * 128;
    const int bm = blockIdx.y * 128;
    const int t  = threadIdx.x;
    const int lane = t & 31;
    const int w  = t >> 5;
    const int wm = (w >> 2) * 64;    // 0 or 64
    const int wn = (w & 3) * 32;     // 0,32,64,96

    if (t < 128) {
        int m = bm + t;
        rows[t] = x[(m & 63) * S_LEN + (m >> 6)] * HID;
    }
    __syncthreads();

    float acc[4][4][4];
#pragma unroll
    for (int i = 0; i < 4; i++)
#pragma unroll
        for (int j = 0; j < 4; j++)
#pragma unroll
            for (int k = 0; k < 4; k++) acc[i][j][k] = 0.f;

    // staging indices
    const int ar = t >> 1, ak = (t & 1) * 16;          // A: row, k-seg
    const int bk = t >> 3, bn0 = (t & 7) * 16;         // B: k-row, n-seg

    for (int k0 = 0; k0 < HID; k0 += 32) {
        __syncthreads();
        // stage A (gathered embed rows), split hi/lo
#pragma unroll
        for (int i = 0; i < 4; i++) {
            float4 v = *(const float4*)&embed[rows[ar] + k0 + ak + i * 4];
            uint32_t h0, h1, l0, l1; split4(v, h0, h1, l0, l1);
            *(uint2*)&AsH[ar][ak + i * 4] = make_uint2(h0, h1);
            *(uint2*)&AsL[ar][ak + i * 4] = make_uint2(l0, l1);
        }
        // stage B (Wi), split hi/lo
        {
            uint32_t hh[8], ll[8];
#pragma unroll
            for (int i = 0; i < 4; i++) {
                float4 v = *(const float4*)&Wi[(size_t)(k0 + bk) * G4 + bn + bn0 + i * 4];
                split4(v, hh[i * 2], hh[i * 2 + 1], ll[i * 2], ll[i * 2 + 1]);
            }
            *(uint4*)&BsH[bk][bn0]     = make_uint4(hh[0], hh[1], hh[2], hh[3]);
            *(uint4*)&BsH[bk][bn0 + 8] = make_uint4(hh[4], hh[5], hh[6], hh[7]);
            *(uint4*)&BsL[bk][bn0]     = make_uint4(ll[0], ll[1], ll[2], ll[3]);
            *(uint4*)&BsL[bk][bn0 + 8] = make_uint4(ll[4], ll[5], ll[6], ll[7]);
        }
        __syncthreads();

#pragma unroll
        for (int k16 = 0; k16 < 2; k16++) {
            uint32_t bH[4][2], bL[4][2];
#pragma unroll
            for (int p = 0; p < 2; p++) {
                int krow = k16 * 16 + (lane & 15);
                int ncol = wn + p * 16 + (lane >> 4) * 8;
                uint32_t r0, r1, r2, r3;
                ldsm_x4t(smem_u32(&BsH[krow][ncol]), r0, r1, r2, r3);
                bH[p * 2][0] = r0; bH[p * 2][1] = r1;
                bH[p * 2 + 1][0] = r2; bH[p * 2 + 1][1] = r3;
                ldsm_x4t(smem_u32(&BsL[krow][ncol]), r0, r1, r2, r3);
                bL[p * 2][0] = r0; bL[p * 2][1] = r1;
                bL[p * 2 + 1][0] = r2; bL[p * 2 + 1][1] = r3;
            }
#pragma unroll
            for (int mf = 0; mf < 4; mf++) {
                int arow = wm + mf * 16 + (lane & 15);
                int acol = k16 * 16 + (lane >> 4) * 8;
                uint32_t aH[4], aL[4];
                ldsm_x4(smem_u32(&AsH[arow][acol]), aH[0], aH[1], aH[2], aH[3]);
                ldsm_x4(smem_u32(&AsL[arow][acol]), aL[0], aL[1], aL[2], aL[3]);
#pragma unroll
                for (int nf = 0; nf < 4; nf++) {
                    mma16816(acc[mf][nf], aH, bH[nf]);
                    mma16816(acc[mf][nf], aH, bL[nf]);
                    mma16816(acc[mf][nf], aL, bH[nf]);
                }
            }
        }
    }

    // epilogue
#pragma unroll
    for (int mf = 0; mf < 4; mf++) {
        int gm = bm + wm + mf * 16 + (lane >> 2);
#pragma unroll
        for (int nf = 0; nf < 4; nf++) {
            int gn = bn + wn + nf * 8 + 2 * (lane & 3);
            *(float2*)&g_gx[(size_t)gm * G4 + gn] =
                make_float2(acc[mf][nf][0], acc[mf][nf][1]);
            *(float2*)&g_gx[(size_t)(gm + 8) * G4 + gn] =
                make_float2(acc[mf][nf][2], acc[mf][nf][3]);
        }
    }
}

// ---------------- persistent scan: Wh slice resident in SMEM -----------------
__device__ __forceinline__ void grid_barrier(unsigned epoch) {
    __syncthreads();
    if (threadIdx.x == 0) {
        __threadfence();
        unsigned prev = atomicAdd(&g_arrive, 1u);
        if (prev + 1u == (unsigned)NBLK * epoch) {
            atomicExch(&g_release, epoch);
        } else {
            unsigned r;
            do {
                asm volatile("ld.acquire.gpu.u32 %0, [%1];"
                             : "=r"(r) : "l"(&g_release) : "memory");
            } while (r < epoch);
        }
    }
    __syncthreads();
}

// dynamic smem layout (floats):
//   Whs[256][32][4]  (k4, col, k-sub)  : 32768
//   Hs [64][132]                        : 8448
//   gsm[32][65]                         : 2080
#define WHS_SZ (256 * 32 * 4)
#define HS_STR 132
#define HS_SZ  (64 * HS_STR)
#define GSM_STR 65
#define SCAN_SMEM ((WHS_SZ + HS_SZ + 32 * GSM_STR) * 4)

__global__ __launch_bounds__(512, 1) void scan_kernel(const float* __restrict__ Wh,
                                                      const float* __restrict__ bh) {
    extern __shared__ float sm[];
    float* Whs = sm;                    // [kk4][c][4]
    float* Hs  = sm + WHS_SZ;           // [64][HS_STR]
    float* gsm = Hs + HS_SZ;            // [32][GSM_STR]

    const int t  = threadIdx.x;
    const int j0 = blockIdx.x * UPB;
    const int c  = t & 31;               // column 0..31 (gate*8+unit)
    const int r0 = (t >> 5) * 4;         // 4 rows per thread

    // preload Wh slice: cols = gate*1024 + j0 + u
    for (int idx = t; idx < HID * 32; idx += 512) {
        int k = idx >> 5, cc = idx & 31;
        int col = (cc >> 3) * HID + j0 + (cc & 7);
        Whs[((k >> 2) * 32 + cc) * 4 + (k & 3)] = Wh[(size_t)k * G4 + col];
    }
    // bias for pointwise
    __shared__ float bsm[4][UPB];
    __shared__ float csm[64][UPB];       // cell state resident in smem
    if (t < 32) bsm[t >> 3][t & 7] = bh[(t >> 3) * HID + j0 + (t & 7)];
    if (t < 512) csm[t >> 3][t & 7] = 0.f;
    grid_barrier(1u);   // also orders preload vs first use (global barrier epoch 1)

    const int hl_r = t >> 3, hl_k = (t & 7) * 16;

    for (int s = 0; s < S_LEN; ++s) {
        const float* hbuf = g_h2[s & 1];
        float acc0 = 0.f, acc1 = 0.f, acc2 = 0.f, acc3 = 0.f;

        for (int ch = 0; ch < HID / CH; ch++) {
            __syncthreads();
#pragma unroll
            for (int i = 0; i < 4; i++) {
                float4 v = *(const float4*)&hbuf[hl_r * HID + ch * CH + hl_k + i * 4];
                *(float4*)&Hs[hl_r * HS_STR + hl_k + i * 4] = v;
            }
            __syncthreads();
#pragma unroll 8
            for (int k4 = 0; k4 < CH / 4; k4++) {
                int kk4 = ch * (CH / 4) + k4;
                float4 w4 = *(const float4*)&Whs[(kk4 * 32 + c) * 4];
                float4 h0 = *(const float4*)&Hs[(r0 + 0) * HS_STR + k4 * 4];
                float4 h1 = *(const float4*)&Hs[(r0 + 1) * HS_STR + k4 * 4];
                float4 h2 = *(const float4*)&Hs[(r0 + 2) * HS_STR + k4 * 4];
                float4 h3 = *(const float4*)&Hs[(r0 + 3) * HS_STR + k4 * 4];
                acc0 += h0.x * w4.x + h0.y * w4.y + h0.z * w4.z + h0.w * w4.w;
                acc1 += h1.x * w4.x + h1.y * w4.y + h1.z * w4.z + h1.w * w4.w;
                acc2 += h2.x * w4.x + h2.y * w4.y + h2.z * w4.z + h2.w * w4.w;
                acc3 += h3.x * w4.x + h3.y * w4.y + h3.z * w4.z + h3.w * w4.w;
            }
        }
        __syncthreads();
        gsm[c * GSM_STR + r0 + 0] = acc0;
        gsm[c * GSM_STR + r0 + 1] = acc1;
        gsm[c * GSM_STR + r0 + 2] = acc2;
        gsm[c * GSM_STR + r0 + 3] = acc3;
        __syncthreads();

        // pointwise: thread t -> (b = t>>3, u = t&7)
        {
            int b = t >> 3, u = t & 7;
            int j = j0 + u;
            const float* gx = &g_gx[((size_t)s * B_SZ + b) * G4];
            float gi = gsm[(0 * 8 + u) * GSM_STR + b] + gx[j]           + bsm[0][u];
            float gf = gsm[(1 * 8 + u) * GSM_STR + b] + gx[HID + j]     + bsm[1][u];
            float gv = gsm[(2 * 8 + u) * GSM_STR + b] + gx[2 * HID + j] + bsm[2][u];
            float go = gsm[(3 * 8 + u) * GSM_STR + b] + gx[3 * HID + j] + bsm[3][u];
            gi = 1.f / (1.f + expf(-gi));
            gf = 1.f / (1.f + expf(-gf));
            gv = tanhf(gv);
            go = 1.f / (1.f + expf(-go));
            float cc = gf * csm[b][u] + gi * gv;
            float h = go * tanhf(cc);
            csm[b][u] = cc;
            g_h2[(s + 1) & 1][b * HID + j] = h;
            g_hs[((size_t)b * S_LEN + s) * HID + j] = h;
        }
        grid_barrier((unsigned)(s + 2));
    }
}

// ---------------- phase 3: logits = hs @ Wo + bo -----------------------------
__global__ __launch_bounds__(256) void gemm_logits(const float* __restrict__ Wo,
                                                   const float* __restrict__ bo,
                                                   float* __restrict__ out) {
    __shared__ float As[8][128];
    __shared__ float Bs[8][64];

    const int bn = blockIdx.x * 64;
    const int bm = blockIdx.y * 128;
    const int t  = threadIdx.x;
    const int tx = t & 15, ty = t >> 4;

    float acc[8][4];
#pragma unroll
    for (int i = 0; i < 8; i++)
#pragma unroll
        for (int j = 0; j < 4; j++) acc[i][j] = 0.f;

    const int la_r = t >> 1;
    const int la_k = (t & 1) * 4;
    const int lb_k = t >> 5;
    const int lb_n = (t & 31) * 2;

    for (int k0 = 0; k0 < HID; k0 += 8) {
        __syncthreads();
        float4 av = *(const float4*)&g_hs[(size_t)(bm + la_r) * HID + k0 + la_k];
        As[la_k + 0][la_r] = av.x;
        As[la_k + 1][la_r] = av.y;
        As[la_k + 2][la_r] = av.z;
        As[la_k + 3][la_r] = av.w;
        float2 bv = *(const float2*)&Wo[(k0 + lb_k) * NACT + bn + lb_n];
        *(float2*)&Bs[lb_k][lb_n] = bv;
        __syncthreads();
#pragma unroll
        for (int kk = 0; kk < 8; kk++) {
            float4 a0 = *(const float4*)&As[kk][ty * 8];
            float4 a1 = *(const float4*)&As[kk][ty * 8 + 4];
            float4 b0 = *(const float4*)&Bs[kk][tx * 4];
            float a[8] = {a0.x, a0.y, a0.z, a0.w, a1.x, a1.y, a1.z, a1.w};
            float b[4] = {b0.x, b0.y, b0.z, b0.w};
#pragma unroll
            for (int i = 0; i < 8; i++)
#pragma unroll
                for (int j = 0; j < 4; j++) acc[i][j] += a[i] * b[j];
        }
    }
    float b0 = bo[bn + tx * 4 + 0];
    float b1 = bo[bn + tx * 4 + 1];
    float b2 = bo[bn + tx * 4 + 2];
    float b3 = bo[bn + tx * 4 + 3];
#pragma unroll
    for (int i = 0; i < 8; i++) {
        float4 v = make_float4(acc[i][0] + b0, acc[i][1] + b1,
                               acc[i][2] + b2, acc[i][3] + b3);
        *(float4*)&out[(size_t)(bm + ty * 8 + i) * NACT + bn + tx * 4] = v;
    }
}

// ---------------- launch -----------------------------------------------------
extern "C" void kernel_launch(void* const* d_in, const int* in_sizes, int n_in,
                              void* d_out, int out_size) {
    const float* embed = (const float*)d_in[0];
    const float* Wi    = (const float*)d_in[1];
    const float* Wh    = (const float*)d_in[2];
    const float* bh    = (const float*)d_in[3];
    const float* Wo    = (const float*)d_in[4];
    const float* bo    = (const float*)d_in[5];
    const int*   x     = (const int*)d_in[6];
    float* out = (float*)d_out;

    int has_dummy = (out_size == B_SZ * S_LEN * (NACT + 2)) ? 1 : 0;
    int logits_off = has_dummy ? B_SZ * S_LEN : 0;

    static int smem_set = 0;
    if (!smem_set) {
        cudaFuncSetAttribute(scan_kernel,
                             cudaFuncAttributeMaxDynamicSharedMemorySize, SCAN_SMEM);
        smem_set = 1;
    }

    init_kernel<<<256, 256>>>(out, has_dummy);
    gemm_gx<<<dim3(G4 / 128, (S_LEN * B_SZ) / 128), 256>>>(embed, Wi, x);
    scan_kernel<<<NBLK, 512, SCAN_SMEM>>>(Wh, bh);
    gemm_logits<<<dim3(NACT / 64, (S_LEN * B_SZ) / 128), 256>>>(Wo, bo, out + logits_off);
}

// round 4
// speedup vs baseline: 2.9832x; 2.2851x over previous
#include <cuda_runtime.h>
#include <cuda_bf16.h>
#include <math.h>
#include <stdint.h>

#define S_LEN 512
#define B_SZ  64
#define HID   1024
#define G4    4096
#define NACT  128
#define NBLK  128       // persistent scan blocks
#define UPB   8         // hidden units per scan block

// ---------------- scratch ----------------------------------------------------
__device__ float g_gx[(size_t)S_LEN * B_SZ * G4];   // [s][b][4H]
__device__ float g_hs[(size_t)B_SZ * S_LEN * HID];  // [b][s][H]
__device__ __nv_bfloat16 g_hbf[2][2][B_SZ * HID];   // [buf][hi/lo][b*H+j]
__device__ unsigned g_arrive;
__device__ unsigned g_release;

// ---------------- init -------------------------------------------------------
__global__ void init_kernel(float* __restrict__ out, int has_dummy) {
    int i = blockIdx.x * 256 + threadIdx.x;          // 65536 threads
    g_hbf[0][0][i] = __float2bfloat16(0.f);
    g_hbf[0][1][i] = __float2bfloat16(0.f);
    if (i == 0) { g_arrive = 0u; g_release = 0u; }
    if (has_dummy && i < 2 * B_SZ * S_LEN) {
        int off = (i < B_SZ * S_LEN) ? i : (B_SZ * S_LEN * NACT + i);
        out[off] = 0.f;
    }
}

// ---------------- mma helpers ------------------------------------------------
__device__ __forceinline__ uint32_t smem_u32(const void* p) {
    return (uint32_t)__cvta_generic_to_shared(p);
}
__device__ __forceinline__ void ldsm_x4(uint32_t a, uint32_t& r0, uint32_t& r1,
                                        uint32_t& r2, uint32_t& r3) {
    asm volatile("ldmatrix.sync.aligned.m8n8.x4.shared.b16 {%0,%1,%2,%3}, [%4];"
                 : "=r"(r0), "=r"(r1), "=r"(r2), "=r"(r3) : "r"(a));
}
__device__ __forceinline__ void ldsm_x4t(uint32_t a, uint32_t& r0, uint32_t& r1,
                                         uint32_t& r2, uint32_t& r3) {
    asm volatile("ldmatrix.sync.aligned.m8n8.x4.trans.shared.b16 {%0,%1,%2,%3}, [%4];"
                 : "=r"(r0), "=r"(r1), "=r"(r2), "=r"(r3) : "r"(a));
}
__device__ __forceinline__ void mma16816(float* c, const uint32_t* a, const uint32_t* b) {
    asm volatile("mma.sync.aligned.m16n8k16.row.col.f32.bf16.bf16.f32 "
                 "{%0,%1,%2,%3},{%4,%5,%6,%7},{%8,%9},{%0,%1,%2,%3};"
                 : "+f"(c[0]), "+f"(c[1]), "+f"(c[2]), "+f"(c[3])
                 : "r"(a[0]), "r"(a[1]), "r"(a[2]), "r"(a[3]), "r"(b[0]), "r"(b[1]));
}
__device__ __forceinline__ uint32_t packbf(__nv_bfloat16 lo, __nv_bfloat16 hi) {
    return (uint32_t)__bfloat16_as_ushort(lo) | ((uint32_t)__bfloat16_as_ushort(hi) << 16);
}
__device__ __forceinline__ void split4(float4 v, uint32_t& h0, uint32_t& h1,
                                       uint32_t& l0, uint32_t& l1) {
    __nv_bfloat16 a = __float2bfloat16(v.x), b = __float2bfloat16(v.y);
    __nv_bfloat16 c = __float2bfloat16(v.z), d = __float2bfloat16(v.w);
    __nv_bfloat16 ra = __float2bfloat16(v.x - __bfloat162float(a));
    __nv_bfloat16 rb = __float2bfloat16(v.y - __bfloat162float(b));
    __nv_bfloat16 rc = __float2bfloat16(v.z - __bfloat162float(c));
    __nv_bfloat16 rd = __float2bfloat16(v.w - __bfloat162float(d));
    h0 = packbf(a, b); h1 = packbf(c, d);
    l0 = packbf(ra, rb); l1 = packbf(rc, rd);
}

// ---------------- phase 1: gx = embed[x] @ Wi (bf16-split tensor cores) ------
#define ASTR 40
#define BSTR 136
__global__ __launch_bounds__(256) void gemm_gx(const float* __restrict__ embed,
                                               const float* __restrict__ Wi,
                                               const int*   __restrict__ x) {
    __shared__ __align__(16) unsigned short AsH[128][ASTR];
    __shared__ __align__(16) unsigned short AsL[128][ASTR];
    __shared__ __align__(16) unsigned short BsH[32][BSTR];
    __shared__ __align__(16) unsigned short BsL[32][BSTR];
    __shared__ int rows[128];

    const int bn = blockIdx.x * 128;
    const int bm = blockIdx.y * 128;
    const int t  = threadIdx.x;
    const int lane = t & 31;
    const int w  = t >> 5;
    const int wm = (w >> 2) * 64;
    const int wn = (w & 3) * 32;

    if (t < 128) {
        int m = bm + t;
        rows[t] = x[(m & 63) * S_LEN + (m >> 6)] * HID;
    }
    __syncthreads();

    float acc[4][4][4];
#pragma unroll
    for (int i = 0; i < 4; i++)
#pragma unroll
        for (int j = 0; j < 4; j++)
#pragma unroll
            for (int k = 0; k < 4; k++) acc[i][j][k] = 0.f;

    const int ar = t >> 1, ak = (t & 1) * 16;
    const int bk = t >> 3, bn0 = (t & 7) * 16;

    for (int k0 = 0; k0 < HID; k0 += 32) {
        __syncthreads();
#pragma unroll
        for (int i = 0; i < 4; i++) {
            float4 v = *(const float4*)&embed[rows[ar] + k0 + ak + i * 4];
            uint32_t h0, h1, l0, l1; split4(v, h0, h1, l0, l1);
            *(uint2*)&AsH[ar][ak + i * 4] = make_uint2(h0, h1);
            *(uint2*)&AsL[ar][ak + i * 4] = make_uint2(l0, l1);
        }
        {
            uint32_t hh[8], ll[8];
#pragma unroll
            for (int i = 0; i < 4; i++) {
                float4 v = *(const float4*)&Wi[(size_t)(k0 + bk) * G4 + bn + bn0 + i * 4];
                split4(v, hh[i * 2], hh[i * 2 + 1], ll[i * 2], ll[i * 2 + 1]);
            }
            *(uint4*)&BsH[bk][bn0]     = make_uint4(hh[0], hh[1], hh[2], hh[3]);
            *(uint4*)&BsH[bk][bn0 + 8] = make_uint4(hh[4], hh[5], hh[6], hh[7]);
            *(uint4*)&BsL[bk][bn0]     = make_uint4(ll[0], ll[1], ll[2], ll[3]);
            *(uint4*)&BsL[bk][bn0 + 8] = make_uint4(ll[4], ll[5], ll[6], ll[7]);
        }
        __syncthreads();

#pragma unroll
        for (int k16 = 0; k16 < 2; k16++) {
            uint32_t bH[4][2], bL[4][2];
#pragma unroll
            for (int p = 0; p < 2; p++) {
                int krow = k16 * 16 + (lane & 15);
                int ncol = wn + p * 16 + (lane >> 4) * 8;
                uint32_t r0, r1, r2, r3;
                ldsm_x4t(smem_u32(&BsH[krow][ncol]), r0, r1, r2, r3);
                bH[p * 2][0] = r0; bH[p * 2][1] = r1;
                bH[p * 2 + 1][0] = r2; bH[p * 2 + 1][1] = r3;
                ldsm_x4t(smem_u32(&BsL[krow][ncol]), r0, r1, r2, r3);
                bL[p * 2][0] = r0; bL[p * 2][1] = r1;
                bL[p * 2 + 1][0] = r2; bL[p * 2 + 1][1] = r3;
            }
#pragma unroll
            for (int mf = 0; mf < 4; mf++) {
                int arow = wm + mf * 16 + (lane & 15);
                int acol = k16 * 16 + (lane >> 4) * 8;
                uint32_t aH[4], aL[4];
                ldsm_x4(smem_u32(&AsH[arow][acol]), aH[0], aH[1], aH[2], aH[3]);
                ldsm_x4(smem_u32(&AsL[arow][acol]), aL[0], aL[1], aL[2], aL[3]);
#pragma unroll
                for (int nf = 0; nf < 4; nf++) {
                    mma16816(acc[mf][nf], aH, bH[nf]);
                    mma16816(acc[mf][nf], aH, bL[nf]);
                    mma16816(acc[mf][nf], aL, bH[nf]);
                }
            }
        }
    }
#pragma unroll
    for (int mf = 0; mf < 4; mf++) {
        int gm = bm + wm + mf * 16 + (lane >> 2);
#pragma unroll
        for (int nf = 0; nf < 4; nf++) {
            int gn = bn + wn + nf * 8 + 2 * (lane & 3);
            *(float2*)&g_gx[(size_t)gm * G4 + gn] =
                make_float2(acc[mf][nf][0], acc[mf][nf][1]);
            *(float2*)&g_gx[(size_t)(gm + 8) * G4 + gn] =
                make_float2(acc[mf][nf][2], acc[mf][nf][3]);
        }
    }
}

// ---------------- persistent tensor-core scan --------------------------------
__device__ __forceinline__ void grid_barrier(unsigned epoch) {
    __syncthreads();
    if (threadIdx.x == 0) {
        __threadfence();
        unsigned prev = atomicAdd(&g_arrive, 1u);
        if (prev + 1u == (unsigned)NBLK * epoch) {
            atomicExch(&g_release, epoch);
        } else {
            unsigned r;
            do {
                asm volatile("ld.acquire.gpu.u32 %0, [%1];"
                             : "=r"(r) : "l"(&g_release) : "memory");
            } while (r < epoch);
        }
    }
    __syncthreads();
}

// dynamic smem: WhF uint4[64 k16][4 gate][32 lane]  = 131072 B
//               Hs  bf16[2 hi/lo][64][136]          =  34816 B
//               gsm f32 [4 ks][64][34]              =  34816 B
#define WHF_BYTES 131072
#define HS_STR 136
#define HS_BYTES 34816
#define GSM_STR 34
#define SCAN_SMEM (WHF_BYTES + HS_BYTES + 34816)

__global__ __launch_bounds__(256, 1) void scan_kernel(const float* __restrict__ Wh,
                                                      const float* __restrict__ bh) {
    extern __shared__ char smraw[];
    uint4* WhF = (uint4*)smraw;                                   // [64][4][32]
    __nv_bfloat16* Hs = (__nv_bfloat16*)(smraw + WHF_BYTES);      // [2][64][136]
    float* gsm = (float*)(smraw + WHF_BYTES + HS_BYTES);          // [4][64][34]
    __shared__ float bsm[4][UPB];
    __shared__ float csm[64][UPB];

    const int t = threadIdx.x, lane = t & 31, w = t >> 5;
    const int mg = w & 1, ks = w >> 1;        // 2 m-groups x 4 k-splits
    const int j0 = blockIdx.x * UPB;

    // ---- preload Wh slice into fragment-ordered SMEM (once) ----
    __nv_bfloat16* tileH = Hs;                // [128][40] temp
    __nv_bfloat16* tileL = Hs + 128 * 40;
    for (int kc = 0; kc < 8; kc++) {
        __syncthreads();
#pragma unroll
        for (int i = 0; i < 16; i++) {
            int idx = i * 256 + t;            // 0..4095
            int kl = idx >> 5, cc = idx & 31;
            float v = Wh[(size_t)(kc * 128 + kl) * G4 + (cc >> 3) * HID + j0 + (cc & 7)];
            __nv_bfloat16 hi = __float2bfloat16(v);
            __nv_bfloat16 lo = __float2bfloat16(v - __bfloat162float(hi));
            tileH[kl * 40 + cc] = hi;
            tileL[kl * 40 + cc] = lo;
        }
        __syncthreads();
        {
            int krow = w * 16 + (lane & 15);
#pragma unroll
            for (int p = 0; p < 2; p++) {
                int ncol = p * 16 + (lane >> 4) * 8;
                uint32_t h0, h1, h2, h3, l0, l1, l2, l3;
                ldsm_x4t(smem_u32(&tileH[krow * 40 + ncol]), h0, h1, h2, h3);
                ldsm_x4t(smem_u32(&tileL[krow * 40 + ncol]), l0, l1, l2, l3);
                WhF[((kc * 8 + w) * 4 + p * 2 + 0) * 32 + lane] = make_uint4(h0, h1, l0, l1);
                WhF[((kc * 8 + w) * 4 + p * 2 + 1) * 32 + lane] = make_uint4(h2, h3, l2, l3);
            }
        }
    }
    if (t < 32) bsm[t >> 3][t & 7] = bh[(t >> 3) * HID + j0 + (t & 7)];
    for (int e = t; e < 512; e += 256) csm[e >> 3][e & 7] = 0.f;
    grid_barrier(1u);

    // ---- 512 steps ----
    for (int s = 0; s < S_LEN; ++s) {
        // prefetch gx gate projections for this block's elems (hide DRAM latency)
        float gxv[2][4];
#pragma unroll
        for (int e2 = 0; e2 < 2; e2++) {
            int e = t + e2 * 256, b = e >> 3, u = e & 7;
            const float* gx = &g_gx[((size_t)s * B_SZ + b) * G4 + j0 + u];
            gxv[e2][0] = gx[0];
            gxv[e2][1] = gx[HID];
            gxv[e2][2] = gx[2 * HID];
            gxv[e2][3] = gx[3 * HID];
        }

        float acc[2][4][4];
#pragma unroll
        for (int mi = 0; mi < 2; mi++)
#pragma unroll
            for (int g = 0; g < 4; g++)
#pragma unroll
                for (int r = 0; r < 4; r++) acc[mi][g][r] = 0.f;

        const __nv_bfloat16* hsrc0 = &g_hbf[s & 1][0][0];
        const __nv_bfloat16* hsrc1 = &g_hbf[s & 1][1][0];

        for (int ch = 0; ch < 8; ch++) {
            __syncthreads();
            // stage 64x128 hi + lo (2048 x 16B)
#pragma unroll
            for (int i = 0; i < 8; i++) {
                int idx = i * 256 + t;
                int hl = idx >> 10, rem = idx & 1023, b = rem >> 4, sg = rem & 15;
                const __nv_bfloat16* src = hl ? hsrc1 : hsrc0;
                uint4 v = *(const uint4*)&src[b * HID + ch * 128 + sg * 8];
                *(uint4*)&Hs[(hl * 64 + b) * HS_STR + sg * 8] = v;
            }
            __syncthreads();
#pragma unroll
            for (int kk = 0; kk < 2; kk++) {
                int kl = ks * 2 + kk;
                uint32_t bhf[4][2], blf[4][2];
#pragma unroll
                for (int g = 0; g < 4; g++) {
                    uint4 f = WhF[((ch * 8 + kl) * 4 + g) * 32 + lane];
                    bhf[g][0] = f.x; bhf[g][1] = f.y;
                    blf[g][0] = f.z; blf[g][1] = f.w;
                }
                uint32_t aH[2][4], aL[2][4];
#pragma unroll
                for (int mi = 0; mi < 2; mi++) {
                    int arow = mg * 32 + mi * 16 + (lane & 15);
                    int acol = kl * 16 + (lane >> 4) * 8;
                    ldsm_x4(smem_u32(&Hs[(0 * 64 + arow) * HS_STR + acol]),
                            aH[mi][0], aH[mi][1], aH[mi][2], aH[mi][3]);
                    ldsm_x4(smem_u32(&Hs[(1 * 64 + arow) * HS_STR + acol]),
                            aL[mi][0], aL[mi][1], aL[mi][2], aL[mi][3]);
                }
#pragma unroll
                for (int mi = 0; mi < 2; mi++)
#pragma unroll
                    for (int g = 0; g < 4; g++) {
                        mma16816(acc[mi][g], aH[mi], bhf[g]);
                        mma16816(acc[mi][g], aH[mi], blf[g]);
                        mma16816(acc[mi][g], aL[mi], bhf[g]);
                    }
            }
        }
        __syncthreads();
        // store k-split partials
#pragma unroll
        for (int mi = 0; mi < 2; mi++)
#pragma unroll
            for (int g = 0; g < 4; g++) {
                int m = mg * 32 + mi * 16 + (lane >> 2);
                int n = g * 8 + (lane & 3) * 2;
                *(float2*)&gsm[(ks * 64 + m) * GSM_STR + n] =
                    make_float2(acc[mi][g][0], acc[mi][g][1]);
                *(float2*)&gsm[(ks * 64 + m + 8) * GSM_STR + n] =
                    make_float2(acc[mi][g][2], acc[mi][g][3]);
            }
        __syncthreads();

        // pointwise
#pragma unroll
        for (int e2 = 0; e2 < 2; e2++) {
            int e = t + e2 * 256, b = e >> 3, u = e & 7, j = j0 + u;
            float gi = gxv[e2][0] + bsm[0][u];
            float gf = gxv[e2][1] + bsm[1][u];
            float gv = gxv[e2][2] + bsm[2][u];
            float go = gxv[e2][3] + bsm[3][u];
#pragma unroll
            for (int p = 0; p < 4; p++) {
                const float* gr = &gsm[(p * 64 + b) * GSM_STR];
                gi += gr[u];
                gf += gr[8 + u];
                gv += gr[16 + u];
                go += gr[24 + u];
            }
            gi = 1.f / (1.f + expf(-gi));
            gf = 1.f / (1.f + expf(-gf));
            gv = tanhf(gv);
            go = 1.f / (1.f + expf(-go));
            float c = gf * csm[b][u] + gi * gv;
            float h = go * tanhf(c);
            csm[b][u] = c;
            __nv_bfloat16 hh = __float2bfloat16(h);
            __nv_bfloat16 hl = __float2bfloat16(h - __bfloat162float(hh));
            g_hbf[(s + 1) & 1][0][b * HID + j] = hh;
            g_hbf[(s + 1) & 1][1][b * HID + j] = hl;
            g_hs[((size_t)b * S_LEN + s) * HID + j] = h;
        }
        grid_barrier((unsigned)(s + 2));
    }
}

// ---------------- phase 3: logits = hs @ Wo + bo -----------------------------
__global__ __launch_bounds__(256) void gemm_logits(const float* __restrict__ Wo,
                                                   const float* __restrict__ bo,
                                                   float* __restrict__ out) {
    __shared__ float As[8][128];
    __shared__ float Bs[8][64];

    const int bn = blockIdx.x * 64;
    const int bm = blockIdx.y * 128;
    const int t  = threadIdx.x;
    const int tx = t & 15, ty = t >> 4;

    float acc[8][4];
#pragma unroll
    for (int i = 0; i < 8; i++)
#pragma unroll
        for (int j = 0; j < 4; j++) acc[i][j] = 0.f;

    const int la_r = t >> 1;
    const int la_k = (t & 1) * 4;
    const int lb_k = t >> 5;
    const int lb_n = (t & 31) * 2;

    for (int k0 = 0; k0 < HID; k0 += 8) {
        __syncthreads();
        float4 av = *(const float4*)&g_hs[(size_t)(bm + la_r) * HID + k0 + la_k];
        As[la_k + 0][la_r] = av.x;
        As[la_k + 1][la_r] = av.y;
        As[la_k + 2][la_r] = av.z;
        As[la_k + 3][la_r] = av.w;
        float2 bv = *(const float2*)&Wo[(k0 + lb_k) * NACT + bn + lb_n];
        *(float2*)&Bs[lb_k][lb_n] = bv;
        __syncthreads();
#pragma unroll
        for (int kk = 0; kk < 8; kk++) {
            float4 a0 = *(const float4*)&As[kk][ty * 8];
            float4 a1 = *(const float4*)&As[kk][ty * 8 + 4];
            float4 b0 = *(const float4*)&Bs[kk][tx * 4];
            float a[8] = {a0.x, a0.y, a0.z, a0.w, a1.x, a1.y, a1.z, a1.w};
            float b[4] = {b0.x, b0.y, b0.z, b0.w};
#pragma unroll
            for (int i = 0; i < 8; i++)
#pragma unroll
                for (int j = 0; j < 4; j++) acc[i][j] += a[i] * b[j];
        }
    }
    float b0 = bo[bn + tx * 4 + 0];
    float b1 = bo[bn + tx * 4 + 1];
    float b2 = bo[bn + tx * 4 + 2];
    float b3 = bo[bn + tx * 4 + 3];
#pragma unroll
    for (int i = 0; i < 8; i++) {
        float4 v = make_float4(acc[i][0] + b0, acc[i][1] + b1,
                               acc[i][2] + b2, acc[i][3] + b3);
        *(float4*)&out[(size_t)(bm + ty * 8 + i) * NACT + bn + tx * 4] = v;
    }
}

// ---------------- launch -----------------------------------------------------
extern "C" void kernel_launch(void* const* d_in, const int* in_sizes, int n_in,
                              void* d_out, int out_size) {
    const float* embed = (const float*)d_in[0];
    const float* Wi    = (const float*)d_in[1];
    const float* Wh    = (const float*)d_in[2];
    const float* bh    = (const float*)d_in[3];
    const float* Wo    = (const float*)d_in[4];
    const float* bo    = (const float*)d_in[5];
    const int*   x     = (const int*)d_in[6];
    float* out = (float*)d_out;

    int has_dummy = (out_size == B_SZ * S_LEN * (NACT + 2)) ? 1 : 0;
    int logits_off = has_dummy ? B_SZ * S_LEN : 0;

    static int smem_set = 0;
    if (!smem_set) {
        cudaFuncSetAttribute(scan_kernel,
                             cudaFuncAttributeMaxDynamicSharedMemorySize, SCAN_SMEM);
        smem_set = 1;
    }

    init_kernel<<<256, 256>>>(out, has_dummy);
    gemm_gx<<<dim3(G4 / 128, (S_LEN * B_SZ) / 128), 256>>>(embed, Wi, x);
    scan_kernel<<<NBLK, 256, SCAN_SMEM>>>(Wh, bh);
    gemm_logits<<<dim3(NACT / 64, (S_LEN * B_SZ) / 128), 256>>>(Wo, bo, out + logits_off);
}